// round 1
// baseline (speedup 1.0000x reference)
#include <cuda_runtime.h>

#define WS   14
#define NTOK 196
#define DIM  768
#define NH   12
#define HD   64
#define BATCH 256
#define M1   (BATCH * NTOK)   // 50176 rows
#define QKVC (3 * DIM)        // 2304

// Scratch: static device arrays (no runtime allocation allowed).
__device__ float g_qkv[M1 * QKVC];  // [50176, 2304]  q|k|v channel-major
__device__ float g_att[M1 * DIM];   // [50176, 768]   attention output

// ---------------------------------------------------------------------------
// NT SGEMM: C[m,n] = sum_k A[m,k] * W[n,k] (+ bias[n])
// 128x128 tile, BK=8, 256 threads, 8x8 microtile with split-float4 layout
// (rows r4*4 / r4*4+64, cols c4*4 / c4*4+64) for conflict-free LDS.128.
// Requires M%128==0, N%128==0, K%8==0 (true for all three GEMMs here).
// ---------------------------------------------------------------------------
__global__ __launch_bounds__(256) void sgemm_nt(
    const float* __restrict__ A, const float* __restrict__ W,
    const float* __restrict__ bias, float* __restrict__ C,
    int M, int N, int K)
{
    __shared__ float As[8][128];
    __shared__ float Ws[8][128];

    const int tid  = threadIdx.x;
    const int bm   = blockIdx.y * 128;
    const int bn   = blockIdx.x * 128;
    const int lrow = tid >> 1;          // 0..127
    const int lcol = (tid & 1) << 2;    // 0 or 4
    const int r4   = tid >> 4;          // 0..15
    const int c4   = tid & 15;          // 0..15

    const float* Ag = A + (size_t)(bm + lrow) * K + lcol;
    const float* Wg = W + (size_t)(bn + lrow) * K + lcol;

    float acc[2][2][4][4];              // [rowhalf][colhalf][ri][ci]
    #pragma unroll
    for (int a = 0; a < 2; a++)
        #pragma unroll
        for (int b = 0; b < 2; b++)
            #pragma unroll
            for (int i = 0; i < 4; i++)
                #pragma unroll
                for (int j = 0; j < 4; j++) acc[a][b][i][j] = 0.f;

    for (int k0 = 0; k0 < K; k0 += 8) {
        float4 av = *(const float4*)(Ag + k0);
        float4 wv = *(const float4*)(Wg + k0);
        __syncthreads();  // previous iteration's reads must finish
        As[lcol + 0][lrow] = av.x; As[lcol + 1][lrow] = av.y;
        As[lcol + 2][lrow] = av.z; As[lcol + 3][lrow] = av.w;
        Ws[lcol + 0][lrow] = wv.x; Ws[lcol + 1][lrow] = wv.y;
        Ws[lcol + 2][lrow] = wv.z; Ws[lcol + 3][lrow] = wv.w;
        __syncthreads();

        #pragma unroll
        for (int k = 0; k < 8; k++) {
            float4 a0 = *(const float4*)&As[k][r4 * 4];
            float4 a1 = *(const float4*)&As[k][r4 * 4 + 64];
            float4 b0 = *(const float4*)&Ws[k][c4 * 4];
            float4 b1 = *(const float4*)&Ws[k][c4 * 4 + 64];
            float ar[2][4] = {{a0.x, a0.y, a0.z, a0.w}, {a1.x, a1.y, a1.z, a1.w}};
            float br[2][4] = {{b0.x, b0.y, b0.z, b0.w}, {b1.x, b1.y, b1.z, b1.w}};
            #pragma unroll
            for (int rh = 0; rh < 2; rh++)
                #pragma unroll
                for (int ch = 0; ch < 2; ch++)
                    #pragma unroll
                    for (int ri = 0; ri < 4; ri++)
                        #pragma unroll
                        for (int ci = 0; ci < 4; ci++)
                            acc[rh][ch][ri][ci] =
                                fmaf(ar[rh][ri], br[ch][ci], acc[rh][ch][ri][ci]);
        }
    }

    #pragma unroll
    for (int rh = 0; rh < 2; rh++)
        #pragma unroll
        for (int ri = 0; ri < 4; ri++) {
            int row = bm + r4 * 4 + rh * 64 + ri;
            float* Cr = C + (size_t)row * N + bn;
            #pragma unroll
            for (int ch = 0; ch < 2; ch++) {
                int col = c4 * 4 + ch * 64;
                float4 o;
                o.x = acc[rh][ch][ri][0]; o.y = acc[rh][ch][ri][1];
                o.z = acc[rh][ch][ri][2]; o.w = acc[rh][ch][ri][3];
                if (bias) {
                    o.x += bias[bn + col + 0]; o.y += bias[bn + col + 1];
                    o.z += bias[bn + col + 2]; o.w += bias[bn + col + 3];
                }
                *(float4*)(Cr + col) = o;
            }
        }
}

// ---------------------------------------------------------------------------
// Local attention: one block per (batch, query), one warp per head.
// Each query attends to its <=9 valid 3x3 neighbors (mask/rel_idx derived
// from geometry, exact vs the reference's -FLT_MAX masking which yields
// exactly-zero softmax weights). Two fp32 channels per lane (HD=64).
// ---------------------------------------------------------------------------
__global__ __launch_bounds__(NH * 32) void local_attn_kernel(
    const float* __restrict__ Y, const float* __restrict__ rpb,
    float* __restrict__ O)
{
    const int bq   = blockIdx.x;          // b*196 + q
    const int q    = bq % NTOK;
    const int qi   = q / WS, qj = q % WS;
    const int h    = threadIdx.x >> 5;
    const int lane = threadIdx.x & 31;

    const size_t base = (size_t)bq * QKVC + h * HD;
    float2 qv = ((const float2*)(Y + base))[lane];
    qv.x *= 0.125f; qv.y *= 0.125f;       // HD^-0.5

    float  logit[9];
    float2 vv[9];
    #pragma unroll
    for (int t = 0; t < 9; t++) {
        const int di = t / 3 - 1, dj = t % 3 - 1;
        const int ki = qi + di, kj = qj + dj;
        const bool ok = ((unsigned)ki < WS) && ((unsigned)kj < WS);  // block-uniform
        float  lg = -1e30f;
        float2 v2 = make_float2(0.f, 0.f);
        if (ok) {
            const size_t kbase = (size_t)(bq + di * WS + dj) * QKVC + h * HD;
            float2 kv = ((const float2*)(Y + kbase + DIM))[lane];
            v2        = ((const float2*)(Y + kbase + 2 * DIM))[lane];
            float p = qv.x * kv.x + qv.y * kv.y;
            #pragma unroll
            for (int off = 16; off > 0; off >>= 1)
                p += __shfl_xor_sync(0xffffffffu, p, off);
            const int rel = (13 - di) * 27 + (13 - dj);  // (qi-ki+13)*27 + (qj-kj+13)
            lg = p + rpb[rel * NH + h];
        }
        logit[t] = lg;
        vv[t]    = v2;
    }

    float m = logit[0];
    #pragma unroll
    for (int t = 1; t < 9; t++) m = fmaxf(m, logit[t]);
    float den = 0.f;
    float2 acc = make_float2(0.f, 0.f);
    #pragma unroll
    for (int t = 0; t < 9; t++) {
        float e = __expf(logit[t] - m);   // invalid -> exp(-huge) == 0 exactly
        den  += e;
        acc.x = fmaf(e, vv[t].x, acc.x);
        acc.y = fmaf(e, vv[t].y, acc.y);
    }
    const float inv = 1.f / den;
    acc.x *= inv; acc.y *= inv;
    ((float2*)(O + (size_t)bq * DIM + h * HD))[lane] = acc;
}

// ---------------------------------------------------------------------------
extern "C" void kernel_launch(void* const* d_in, const int* in_sizes, int n_in,
                              void* d_out, int out_size)
{
    const float* x      = (const float*)d_in[0];  // [B,N,768]
    const float* w_qkv  = (const float*)d_in[1];  // [2304,768]
    const float* rpb    = (const float*)d_in[2];  // [729,12]
    const float* proj_w = (const float*)d_in[3];  // [768,768]
    const float* proj_b = (const float*)d_in[4];  // [768]
    // d_in[5] (mask) and d_in[6] (rel_idx) intentionally unused: derived analytically.
    float* out = (float*)d_out;                   // [B,N,768] fp32

    float *qkv, *att;
    cudaGetSymbolAddress((void**)&qkv, g_qkv);
    cudaGetSymbolAddress((void**)&att, g_att);

    dim3 g1(QKVC / 128, M1 / 128);   // 18 x 392
    sgemm_nt<<<g1, 256>>>(x, w_qkv, nullptr, qkv, M1, QKVC, DIM);

    local_attn_kernel<<<M1, NH * 32>>>(qkv, rpb, att);

    dim3 g3(DIM / 128, M1 / 128);    // 6 x 392
    sgemm_nt<<<g3, 256>>>(att, proj_w, proj_b, out, M1, DIM, DIM);
}

// round 3
// speedup vs baseline: 2.0774x; 2.0774x over previous
#include <cuda_runtime.h>
#include <cuda_bf16.h>
#include <cstdint>

#define WS    14
#define NTOK  196
#define DIM   768
#define NH    12
#define HD    64
#define BATCH 256
#define M1    (BATCH * NTOK)   // 50176
#define QKVC  (3 * DIM)        // 2304
#define K_TOT 768

// ---------------- scratch (static device arrays; no runtime alloc) ----------
__device__ float         g_qkv[(size_t)M1 * QKVC];
__device__ __nv_bfloat16 g_xh[(size_t)M1 * DIM];
__device__ __nv_bfloat16 g_xl[(size_t)M1 * DIM];
__device__ __nv_bfloat16 g_ah[(size_t)M1 * DIM];
__device__ __nv_bfloat16 g_al[(size_t)M1 * DIM];
__device__ __nv_bfloat16 g_wqh[(size_t)QKVC * DIM];
__device__ __nv_bfloat16 g_wql[(size_t)QKVC * DIM];
__device__ __nv_bfloat16 g_pwh[(size_t)DIM * DIM];
__device__ __nv_bfloat16 g_pwl[(size_t)DIM * DIM];

// ---------------- PTX helpers (base-target features only) --------------------
__device__ __forceinline__ uint32_t smem_u32(const void* p) {
    uint32_t a;
    asm("{ .reg .u64 t; cvta.to.shared.u64 t, %1; cvt.u32.u64 %0, t; }" : "=r"(a) : "l"(p));
    return a;
}
#define CP_ASYNC16(sa, ga) \
    asm volatile("cp.async.cg.shared.global [%0], [%1], 16;" :: "r"(sa), "l"(ga))
#define CP_COMMIT() asm volatile("cp.async.commit_group;" ::: "memory")
#define CP_WAIT1()  asm volatile("cp.async.wait_group 1;"  ::: "memory")

__device__ __forceinline__ void ldsm_x4(uint32_t& r0, uint32_t& r1, uint32_t& r2,
                                        uint32_t& r3, uint32_t addr) {
    asm volatile("ldmatrix.sync.aligned.m8n8.x4.shared.b16 {%0,%1,%2,%3}, [%4];"
                 : "=r"(r0), "=r"(r1), "=r"(r2), "=r"(r3) : "r"(addr));
}
__device__ __forceinline__ void mma16816(float* d, const uint32_t* a, const uint32_t* b) {
    asm volatile(
        "mma.sync.aligned.m16n8k16.row.col.f32.bf16.bf16.f32 "
        "{%0,%1,%2,%3}, {%4,%5,%6,%7}, {%8,%9}, {%0,%1,%2,%3};"
        : "+f"(d[0]), "+f"(d[1]), "+f"(d[2]), "+f"(d[3])
        : "r"(a[0]), "r"(a[1]), "r"(a[2]), "r"(a[3]), "r"(b[0]), "r"(b[1]));
}

// ---------------- precision split --------------------------------------------
__device__ __forceinline__ void split2(float x, __nv_bfloat16& h, __nv_bfloat16& l) {
    h = __float2bfloat16(x);
    l = __float2bfloat16(x - __bfloat162float(h));
}

__global__ __launch_bounds__(256) void split_kernel(
    const float* __restrict__ in, __nv_bfloat16* __restrict__ hi,
    __nv_bfloat16* __restrict__ lo, int n4)
{
    int i = blockIdx.x * blockDim.x + threadIdx.x;
    if (i >= n4) return;
    float4 v = ((const float4*)in)[i];
    __nv_bfloat16 h0, h1, h2, h3, l0, l1, l2, l3;
    split2(v.x, h0, l0); split2(v.y, h1, l1);
    split2(v.z, h2, l2); split2(v.w, h3, l3);
    __nv_bfloat162 ha; ha.x = h0; ha.y = h1;
    __nv_bfloat162 hb; hb.x = h2; hb.y = h3;
    __nv_bfloat162 la; la.x = l0; la.y = l1;
    __nv_bfloat162 lb; lb.x = l2; lb.y = l3;
    ((__nv_bfloat162*)hi)[i * 2 + 0] = ha;
    ((__nv_bfloat162*)hi)[i * 2 + 1] = hb;
    ((__nv_bfloat162*)lo)[i * 2 + 0] = la;
    ((__nv_bfloat162*)lo)[i * 2 + 1] = lb;
}

// ---------------- bf16x3 mma.sync GEMM ---------------------------------------
// C[M,N] = A[M,768] * B[N,768]^T (+bias), A/B pre-split into bf16 hi/lo.
// 128x128 CTA tile, BK=32, 8 warps (warp tile 64x32), cp.async double buffer.
// smem rows padded to 80B -> conflict-free ldmatrix (chunk banks 0,5,2,7,4,1,6,3).
#define BKEL   32
#define ROWB   80
#define TILEB  (128 * ROWB)            // 10240 B per operand per stage
#define NCHUNK (3 * (K_TOT / BKEL))    // 72

__global__ __launch_bounds__(256) void gemm_bf16x3_mma(
    const __nv_bfloat16* __restrict__ Ahi, const __nv_bfloat16* __restrict__ Alo,
    const __nv_bfloat16* __restrict__ Bhi, const __nv_bfloat16* __restrict__ Blo,
    const float* __restrict__ bias, float* __restrict__ C, int ldc)
{
    __shared__ __align__(128) char sAbuf[2 * TILEB];
    __shared__ __align__(128) char sBbuf[2 * TILEB];

    const int tid    = threadIdx.x;
    const int lane   = tid & 31;
    const int wid    = tid >> 5;
    const int warp_m = wid >> 2;       // 0..1 -> 64-row half
    const int warp_n = wid & 3;        // 0..3 -> 32-col slice
    const int bm     = blockIdx.y * 128;
    const int bn     = blockIdx.x * 128;

    const uint32_t sA0 = smem_u32(sAbuf);
    const uint32_t sB0 = smem_u32(sBbuf);

    // loader assignment: 512 16B segs per tile, 2 per thread
    const int lrow0 = tid >> 2;          // 0..63
    const int lseg  = (tid & 3) * 16;    // byte offset in 64B row

    auto srcA = [&](int c) -> const __nv_bfloat16* {
        const int pass = c / 24, k0 = (c % 24) * BKEL;
        return ((pass < 2) ? Ahi : Alo) + (size_t)bm * K_TOT + k0;
    };
    auto srcB = [&](int c) -> const __nv_bfloat16* {
        const int pass = c / 24, k0 = (c % 24) * BKEL;
        return ((pass == 1) ? Blo : Bhi) + (size_t)bn * K_TOT + k0;
    };

    auto load_chunk = [&](int c, int stage) {
        const __nv_bfloat16* gA = srcA(c);
        const __nv_bfloat16* gB = srcB(c);
        const uint32_t dA = sA0 + stage * TILEB;
        const uint32_t dB = sB0 + stage * TILEB;
        #pragma unroll
        for (int i = 0; i < 2; i++) {
            const int row = lrow0 + i * 64;
            CP_ASYNC16(dA + row * ROWB + lseg, (const char*)(gA + (size_t)row * K_TOT) + lseg);
            CP_ASYNC16(dB + row * ROWB + lseg, (const char*)(gB + (size_t)row * K_TOT) + lseg);
        }
    };

    float acc[4][4][4];
    #pragma unroll
    for (int mi = 0; mi < 4; mi++)
        #pragma unroll
        for (int nj = 0; nj < 4; nj++)
            #pragma unroll
            for (int e = 0; e < 4; e++) acc[mi][nj][e] = 0.f;

    load_chunk(0, 0); CP_COMMIT();
    load_chunk(1, 1); CP_COMMIT();

    // precomputed ldmatrix lane addressing
    const uint32_t a_row  = warp_m * 64 + (lane & 15);
    const uint32_t a_coff = (lane >> 4) * 16;              // byte: 8 elems * 2
    const uint32_t b_row  = warp_n * 32 + ((lane >> 4) << 3) + (lane & 7);
    const uint32_t b_coff = ((lane >> 3) & 1) * 16;        // k-half byte offset

    #pragma unroll 1
    for (int c = 0; c < NCHUNK; c++) {
        CP_WAIT1();
        __syncthreads();
        const int stage = c & 1;
        const uint32_t sA = sA0 + stage * TILEB;
        const uint32_t sB = sB0 + stage * TILEB;

        #pragma unroll
        for (int kk = 0; kk < 2; kk++) {
            uint32_t a[4][4];
            #pragma unroll
            for (int mi = 0; mi < 4; mi++)
                ldsm_x4(a[mi][0], a[mi][1], a[mi][2], a[mi][3],
                        sA + (a_row + mi * 16) * ROWB + kk * 32 + a_coff);
            uint32_t b[4][2];
            #pragma unroll
            for (int nj2 = 0; nj2 < 2; nj2++) {
                uint32_t r0, r1, r2, r3;
                ldsm_x4(r0, r1, r2, r3,
                        sB + (b_row + nj2 * 16) * ROWB + kk * 32 + b_coff);
                b[nj2 * 2 + 0][0] = r0; b[nj2 * 2 + 0][1] = r1;
                b[nj2 * 2 + 1][0] = r2; b[nj2 * 2 + 1][1] = r3;
            }
            #pragma unroll
            for (int mi = 0; mi < 4; mi++)
                #pragma unroll
                for (int nj = 0; nj < 4; nj++)
                    mma16816(acc[mi][nj], a[mi], b[nj]);
        }
        __syncthreads();
        if (c + 2 < NCHUNK) load_chunk(c + 2, stage);
        CP_COMMIT();
    }

    // epilogue: c-frag thread layout m16n8: rows lane/4 (+8), cols (lane%4)*2
    const int er = lane >> 2;
    const int ec = (lane & 3) * 2;
    #pragma unroll
    for (int mi = 0; mi < 4; mi++) {
        const int r0 = bm + warp_m * 64 + mi * 16 + er;
        #pragma unroll
        for (int nj = 0; nj < 4; nj++) {
            const int col = bn + warp_n * 32 + nj * 8 + ec;
            float2 v0 = make_float2(acc[mi][nj][0], acc[mi][nj][1]);
            float2 v1 = make_float2(acc[mi][nj][2], acc[mi][nj][3]);
            if (bias) {
                const float2 bv = *(const float2*)(bias + col);
                v0.x += bv.x; v0.y += bv.y;
                v1.x += bv.x; v1.y += bv.y;
            }
            *(float2*)(C + (size_t)r0 * ldc + col)       = v0;
            *(float2*)(C + (size_t)(r0 + 8) * ldc + col) = v1;
        }
    }
}

// ---------------- local attention (3x3 neighborhood, exact softmax) ----------
__global__ __launch_bounds__(NH * 32) void local_attn_kernel(
    const float* __restrict__ Y, const float* __restrict__ rpb,
    __nv_bfloat16* __restrict__ Ohi, __nv_bfloat16* __restrict__ Olo)
{
    const int bq   = blockIdx.x;
    const int q    = bq % NTOK;
    const int qi   = q / WS, qj = q % WS;
    const int h    = threadIdx.x >> 5;
    const int lane = threadIdx.x & 31;

    const size_t base = (size_t)bq * QKVC + h * HD;
    float2 qv = ((const float2*)(Y + base))[lane];
    qv.x *= 0.125f; qv.y *= 0.125f;

    float  logit[9];
    float2 vv[9];
    #pragma unroll
    for (int t = 0; t < 9; t++) {
        const int di = t / 3 - 1, dj = t % 3 - 1;
        const int ki = qi + di, kj = qj + dj;
        const bool ok = ((unsigned)ki < WS) && ((unsigned)kj < WS);
        float  lg = -1e30f;
        float2 v2 = make_float2(0.f, 0.f);
        if (ok) {
            const size_t kbase = (size_t)(bq + di * WS + dj) * QKVC + h * HD;
            float2 kv = ((const float2*)(Y + kbase + DIM))[lane];
            v2        = ((const float2*)(Y + kbase + 2 * DIM))[lane];
            float p = qv.x * kv.x + qv.y * kv.y;
            #pragma unroll
            for (int off = 16; off > 0; off >>= 1)
                p += __shfl_xor_sync(0xffffffffu, p, off);
            const int rel = (13 - di) * 27 + (13 - dj);
            lg = p + rpb[rel * NH + h];
        }
        logit[t] = lg;
        vv[t]    = v2;
    }

    float m = logit[0];
    #pragma unroll
    for (int t = 1; t < 9; t++) m = fmaxf(m, logit[t]);
    float den = 0.f;
    float2 acc = make_float2(0.f, 0.f);
    #pragma unroll
    for (int t = 0; t < 9; t++) {
        float e = __expf(logit[t] - m);
        den  += e;
        acc.x = fmaf(e, vv[t].x, acc.x);
        acc.y = fmaf(e, vv[t].y, acc.y);
    }
    const float inv = 1.f / den;
    acc.x *= inv; acc.y *= inv;

    __nv_bfloat16 hx, lx, hy, ly;
    split2(acc.x, hx, lx);
    split2(acc.y, hy, ly);
    __nv_bfloat162 hv; hv.x = hx; hv.y = hy;
    __nv_bfloat162 lv; lv.x = lx; lv.y = ly;
    const size_t obase = (size_t)bq * DIM + h * HD;
    ((__nv_bfloat162*)(Ohi + obase))[lane] = hv;
    ((__nv_bfloat162*)(Olo + obase))[lane] = lv;
}

// ---------------------------------------------------------------------------
extern "C" void kernel_launch(void* const* d_in, const int* in_sizes, int n_in,
                              void* d_out, int out_size)
{
    const float* x      = (const float*)d_in[0];
    const float* w_qkv  = (const float*)d_in[1];
    const float* rpb    = (const float*)d_in[2];
    const float* proj_w = (const float*)d_in[3];
    const float* proj_b = (const float*)d_in[4];
    float* out = (float*)d_out;

    float *qkv;
    __nv_bfloat16 *xh, *xl, *ah, *al, *wqh, *wql, *pwh, *pwl;
    cudaGetSymbolAddress((void**)&qkv, g_qkv);
    cudaGetSymbolAddress((void**)&xh,  g_xh);
    cudaGetSymbolAddress((void**)&xl,  g_xl);
    cudaGetSymbolAddress((void**)&ah,  g_ah);
    cudaGetSymbolAddress((void**)&al,  g_al);
    cudaGetSymbolAddress((void**)&wqh, g_wqh);
    cudaGetSymbolAddress((void**)&wql, g_wql);
    cudaGetSymbolAddress((void**)&pwh, g_pwh);
    cudaGetSymbolAddress((void**)&pwl, g_pwl);

    {
        int n4 = M1 * DIM / 4;
        split_kernel<<<(n4 + 255) / 256, 256>>>(x, xh, xl, n4);
    }
    {
        int n4 = QKVC * DIM / 4;
        split_kernel<<<(n4 + 255) / 256, 256>>>(w_qkv, wqh, wql, n4);
    }
    {
        int n4 = DIM * DIM / 4;
        split_kernel<<<(n4 + 255) / 256, 256>>>(proj_w, pwh, pwl, n4);
    }

    dim3 g1(QKVC / 128, M1 / 128);   // 18 x 392
    gemm_bf16x3_mma<<<g1, 256>>>(xh, xl, wqh, wql, nullptr, qkv, QKVC);

    local_attn_kernel<<<M1, NH * 32>>>(qkv, rpb, ah, al);

    dim3 g3(DIM / 128, M1 / 128);    // 6 x 392
    gemm_bf16x3_mma<<<g3, 256>>>(ah, al, pwh, pwl, proj_b, out, DIM);
}

// round 4
// speedup vs baseline: 3.1927x; 1.5369x over previous
#include <cuda_runtime.h>
#include <cuda_fp16.h>
#include <cstdint>

#define WS    14
#define NTOK  196
#define DIM   768
#define NH    12
#define HD    64
#define BATCH 256
#define M1    (BATCH * NTOK)   // 50176
#define QKVC  (3 * DIM)        // 2304
#define K_TOT 768

// ---------------- scratch (static device arrays; no runtime alloc) ----------
__device__ float  g_qkv[(size_t)M1 * QKVC];
__device__ __half g_xh[(size_t)M1 * DIM];
__device__ __half g_xl[(size_t)M1 * DIM];
__device__ __half g_ah[(size_t)M1 * DIM];
__device__ __half g_al[(size_t)M1 * DIM];
__device__ __half g_wq[(size_t)QKVC * DIM];
__device__ __half g_pw[(size_t)DIM * DIM];

// ---------------- PTX helpers (base-target features only) --------------------
__device__ __forceinline__ uint32_t smem_u32(const void* p) {
    uint32_t a;
    asm("{ .reg .u64 t; cvta.to.shared.u64 t, %1; cvt.u32.u64 %0, t; }" : "=r"(a) : "l"(p));
    return a;
}
#define CP_ASYNC16(sa, ga) \
    asm volatile("cp.async.cg.shared.global [%0], [%1], 16;" :: "r"(sa), "l"(ga))
#define CP_COMMIT() asm volatile("cp.async.commit_group;" ::: "memory")
#define CP_WAIT2()  asm volatile("cp.async.wait_group 2;"  ::: "memory")

__device__ __forceinline__ void ldsm_x4(uint32_t& r0, uint32_t& r1, uint32_t& r2,
                                        uint32_t& r3, uint32_t addr) {
    asm volatile("ldmatrix.sync.aligned.m8n8.x4.shared.b16 {%0,%1,%2,%3}, [%4];"
                 : "=r"(r0), "=r"(r1), "=r"(r2), "=r"(r3) : "r"(addr));
}
__device__ __forceinline__ void mma16816(float* d, const uint32_t* a, const uint32_t* b) {
    asm volatile(
        "mma.sync.aligned.m16n8k16.row.col.f32.f16.f16.f32 "
        "{%0,%1,%2,%3}, {%4,%5,%6,%7}, {%8,%9}, {%0,%1,%2,%3};"
        : "+f"(d[0]), "+f"(d[1]), "+f"(d[2]), "+f"(d[3])
        : "r"(a[0]), "r"(a[1]), "r"(a[2]), "r"(a[3]), "r"(b[0]), "r"(b[1]));
}

// ---------------- precision split (fp16 hi/lo) --------------------------------
__device__ __forceinline__ void splith(float x, __half& h, __half& l) {
    h = __float2half_rn(x);
    l = __float2half_rn(x - __half2float(h));
}

// activations: hi + lo
__global__ __launch_bounds__(256) void split_kernel(
    const float* __restrict__ in, __half* __restrict__ hi,
    __half* __restrict__ lo, int n4)
{
    int i = blockIdx.x * blockDim.x + threadIdx.x;
    if (i >= n4) return;
    float4 v = ((const float4*)in)[i];
    __half h0, h1, h2, h3, l0, l1, l2, l3;
    splith(v.x, h0, l0); splith(v.y, h1, l1);
    splith(v.z, h2, l2); splith(v.w, h3, l3);
    __half2 ha = __halves2half2(h0, h1), hb = __halves2half2(h2, h3);
    __half2 la = __halves2half2(l0, l1), lb = __halves2half2(l2, l3);
    ((__half2*)hi)[i * 2 + 0] = ha;
    ((__half2*)hi)[i * 2 + 1] = hb;
    ((__half2*)lo)[i * 2 + 0] = la;
    ((__half2*)lo)[i * 2 + 1] = lb;
}

// weights: single fp16
__global__ __launch_bounds__(256) void cvt_kernel(
    const float* __restrict__ in, __half* __restrict__ out, int n4)
{
    int i = blockIdx.x * blockDim.x + threadIdx.x;
    if (i >= n4) return;
    float4 v = ((const float4*)in)[i];
    __half2 a = __halves2half2(__float2half_rn(v.x), __float2half_rn(v.y));
    __half2 b = __halves2half2(__float2half_rn(v.z), __float2half_rn(v.w));
    ((__half2*)out)[i * 2 + 0] = a;
    ((__half2*)out)[i * 2 + 1] = b;
}

// ---------------- fp16x2 mma.sync GEMM ---------------------------------------
// C[M,N] = (Ah+Al)[M,768] * W[N,768]^T (+bias), fp32 accumulate.
// 128x128 CTA tile, BK=32, 8 warps (warp tile 64x32), 4-stage cp.async ring,
// one __syncthreads per chunk. smem rows padded to 80B (conflict-free ldmatrix).
#define BKEL   32
#define ROWB   80
#define TILEB  (128 * ROWB)            // 10240 B per operand per stage
#define STAGEB (2 * TILEB)             // A+B per stage
#define NSTG   4
#define GSMEM  (NSTG * STAGEB)         // 81920 B
#define NCHUNK (2 * (K_TOT / BKEL))    // 48

__global__ __launch_bounds__(256, 2) void gemm_fp16x2_mma(
    const __half* __restrict__ Ah, const __half* __restrict__ Al,
    const __half* __restrict__ W,
    const float* __restrict__ bias, float* __restrict__ C, int ldc)
{
    extern __shared__ __align__(128) char smem[];
    const uint32_t s0 = smem_u32(smem);

    const int tid    = threadIdx.x;
    const int lane   = tid & 31;
    const int wid    = tid >> 5;
    const int warp_m = wid >> 2;       // 0..1
    const int warp_n = wid & 3;        // 0..3
    const int bm     = blockIdx.y * 128;
    const int bn     = blockIdx.x * 128;

    const int lrow0 = tid >> 2;          // 0..63
    const int lseg  = (tid & 3) * 16;

    auto srcA = [&](int c) -> const __half* {
        const int pass = c / 24, k0 = (c % 24) * BKEL;
        return (pass ? Al : Ah) + (size_t)bm * K_TOT + k0;
    };
    auto srcB = [&](int c) -> const __half* {
        const int k0 = (c % 24) * BKEL;
        return W + (size_t)bn * K_TOT + k0;
    };

    auto load_chunk = [&](int c, int stage) {
        const __half* gA = srcA(c);
        const __half* gB = srcB(c);
        const uint32_t dA = s0 + stage * STAGEB;
        const uint32_t dB = dA + TILEB;
        #pragma unroll
        for (int i = 0; i < 2; i++) {
            const int row = lrow0 + i * 64;
            CP_ASYNC16(dA + row * ROWB + lseg, (const char*)(gA + (size_t)row * K_TOT) + lseg);
            CP_ASYNC16(dB + row * ROWB + lseg, (const char*)(gB + (size_t)row * K_TOT) + lseg);
        }
    };

    float acc[4][4][4];
    #pragma unroll
    for (int mi = 0; mi < 4; mi++)
        #pragma unroll
        for (int nj = 0; nj < 4; nj++)
            #pragma unroll
            for (int e = 0; e < 4; e++) acc[mi][nj][e] = 0.f;

    load_chunk(0, 0); CP_COMMIT();
    load_chunk(1, 1); CP_COMMIT();
    load_chunk(2, 2); CP_COMMIT();

    const uint32_t a_row  = warp_m * 64 + (lane & 15);
    const uint32_t a_coff = (lane >> 4) * 16;
    const uint32_t b_row  = warp_n * 32 + ((lane >> 4) << 3) + (lane & 7);
    const uint32_t b_coff = ((lane >> 3) & 1) * 16;

    #pragma unroll 1
    for (int c = 0; c < NCHUNK; c++) {
        CP_WAIT2();                     // chunk c's group complete
        __syncthreads();                // + all warps done with stage (c-1)%4
        const int stage = c & 3;
        const uint32_t sA = s0 + stage * STAGEB;
        const uint32_t sB = sA + TILEB;

        #pragma unroll
        for (int kk = 0; kk < 2; kk++) {
            uint32_t a[4][4];
            #pragma unroll
            for (int mi = 0; mi < 4; mi++)
                ldsm_x4(a[mi][0], a[mi][1], a[mi][2], a[mi][3],
                        sA + (a_row + mi * 16) * ROWB + kk * 32 + a_coff);
            uint32_t b[4][2];
            #pragma unroll
            for (int nj2 = 0; nj2 < 2; nj2++) {
                uint32_t r0, r1, r2, r3;
                ldsm_x4(r0, r1, r2, r3,
                        sB + (b_row + nj2 * 16) * ROWB + kk * 32 + b_coff);
                b[nj2 * 2 + 0][0] = r0; b[nj2 * 2 + 0][1] = r1;
                b[nj2 * 2 + 1][0] = r2; b[nj2 * 2 + 1][1] = r3;
            }
            #pragma unroll
            for (int mi = 0; mi < 4; mi++)
                #pragma unroll
                for (int nj = 0; nj < 4; nj++)
                    mma16816(acc[mi][nj], a[mi], b[nj]);
        }
        if (c + 3 < NCHUNK) load_chunk(c + 3, (c + 3) & 3);
        CP_COMMIT();                    // keep group counting uniform
    }

    const int er = lane >> 2;
    const int ec = (lane & 3) * 2;
    #pragma unroll
    for (int mi = 0; mi < 4; mi++) {
        const int r0 = bm + warp_m * 64 + mi * 16 + er;
        #pragma unroll
        for (int nj = 0; nj < 4; nj++) {
            const int col = bn + warp_n * 32 + nj * 8 + ec;
            float2 v0 = make_float2(acc[mi][nj][0], acc[mi][nj][1]);
            float2 v1 = make_float2(acc[mi][nj][2], acc[mi][nj][3]);
            if (bias) {
                const float2 bv = *(const float2*)(bias + col);
                v0.x += bv.x; v0.y += bv.y;
                v1.x += bv.x; v1.y += bv.y;
            }
            *(float2*)(C + (size_t)r0 * ldc + col)       = v0;
            *(float2*)(C + (size_t)(r0 + 8) * ldc + col) = v1;
        }
    }
}

// ---------------- local attention (3x3 neighborhood, exact softmax) ----------
__global__ __launch_bounds__(NH * 32) void local_attn_kernel(
    const float* __restrict__ Y, const float* __restrict__ rpb,
    __half* __restrict__ Ohi, __half* __restrict__ Olo)
{
    const int bq   = blockIdx.x;
    const int q    = bq % NTOK;
    const int qi   = q / WS, qj = q % WS;
    const int h    = threadIdx.x >> 5;
    const int lane = threadIdx.x & 31;

    const size_t base = (size_t)bq * QKVC + h * HD;
    float2 qv = ((const float2*)(Y + base))[lane];
    qv.x *= 0.125f; qv.y *= 0.125f;

    float  logit[9];
    float2 vv[9];
    #pragma unroll
    for (int t = 0; t < 9; t++) {
        const int di = t / 3 - 1, dj = t % 3 - 1;
        const int ki = qi + di, kj = qj + dj;
        const bool ok = ((unsigned)ki < WS) && ((unsigned)kj < WS);
        float  lg = -1e30f;
        float2 v2 = make_float2(0.f, 0.f);
        if (ok) {
            const size_t kbase = (size_t)(bq + di * WS + dj) * QKVC + h * HD;
            float2 kv = ((const float2*)(Y + kbase + DIM))[lane];
            v2        = ((const float2*)(Y + kbase + 2 * DIM))[lane];
            float p = qv.x * kv.x + qv.y * kv.y;
            #pragma unroll
            for (int off = 16; off > 0; off >>= 1)
                p += __shfl_xor_sync(0xffffffffu, p, off);
            const int rel = (13 - di) * 27 + (13 - dj);
            lg = p + rpb[rel * NH + h];
        }
        logit[t] = lg;
        vv[t]    = v2;
    }

    float m = logit[0];
    #pragma unroll
    for (int t = 1; t < 9; t++) m = fmaxf(m, logit[t]);
    float den = 0.f;
    float2 acc = make_float2(0.f, 0.f);
    #pragma unroll
    for (int t = 0; t < 9; t++) {
        float e = __expf(logit[t] - m);
        den  += e;
        acc.x = fmaf(e, vv[t].x, acc.x);
        acc.y = fmaf(e, vv[t].y, acc.y);
    }
    const float inv = 1.f / den;
    acc.x *= inv; acc.y *= inv;

    __half hx, lx, hy, ly;
    splith(acc.x, hx, lx);
    splith(acc.y, hy, ly);
    const size_t obase = (size_t)bq * DIM + h * HD;
    ((__half2*)(Ohi + obase))[lane] = __halves2half2(hx, hy);
    ((__half2*)(Olo + obase))[lane] = __halves2half2(lx, ly);
}

// ---------------------------------------------------------------------------
extern "C" void kernel_launch(void* const* d_in, const int* in_sizes, int n_in,
                              void* d_out, int out_size)
{
    const float* x      = (const float*)d_in[0];
    const float* w_qkv  = (const float*)d_in[1];
    const float* rpb    = (const float*)d_in[2];
    const float* proj_w = (const float*)d_in[3];
    const float* proj_b = (const float*)d_in[4];
    float* out = (float*)d_out;

    float *qkv;
    __half *xh, *xl, *ah, *al, *wq, *pw;
    cudaGetSymbolAddress((void**)&qkv, g_qkv);
    cudaGetSymbolAddress((void**)&xh,  g_xh);
    cudaGetSymbolAddress((void**)&xl,  g_xl);
    cudaGetSymbolAddress((void**)&ah,  g_ah);
    cudaGetSymbolAddress((void**)&al,  g_al);
    cudaGetSymbolAddress((void**)&wq,  g_wq);
    cudaGetSymbolAddress((void**)&pw,  g_pw);

    cudaFuncSetAttribute(gemm_fp16x2_mma,
                         cudaFuncAttributeMaxDynamicSharedMemorySize, GSMEM);

    {
        int n4 = M1 * DIM / 4;
        split_kernel<<<(n4 + 255) / 256, 256>>>(x, xh, xl, n4);
    }
    {
        int n4 = QKVC * DIM / 4;
        cvt_kernel<<<(n4 + 255) / 256, 256>>>(w_qkv, wq, n4);
    }
    {
        int n4 = DIM * DIM / 4;
        cvt_kernel<<<(n4 + 255) / 256, 256>>>(proj_w, pw, n4);
    }

    dim3 g1(QKVC / 128, M1 / 128);   // 18 x 392
    gemm_fp16x2_mma<<<g1, 256, GSMEM>>>(xh, xl, wq, nullptr, qkv, QKVC);

    local_attn_kernel<<<M1, NH * 32>>>(qkv, rpb, ah, al);

    dim3 g3(DIM / 128, M1 / 128);    // 6 x 392
    gemm_fp16x2_mma<<<g3, 256, GSMEM>>>(ah, al, pw, proj_b, out, DIM);
}

// round 5
// speedup vs baseline: 3.4839x; 1.0912x over previous
#include <cuda_runtime.h>
#include <cuda_fp16.h>
#include <cstdint>

#define WS    14
#define NTOK  196
#define DIM   768
#define NH    12
#define HD    64
#define BATCH 256
#define M1    (BATCH * NTOK)   // 50176
#define QKVC  (3 * DIM)        // 2304
#define K_TOT 768

// ---------------- scratch (static device arrays; no runtime alloc) ----------
__device__ float  g_qkv[(size_t)M1 * QKVC];
__device__ __half g_xh[(size_t)M1 * DIM];
__device__ __half g_xl[(size_t)M1 * DIM];
__device__ __half g_ah[(size_t)M1 * DIM];
__device__ __half g_al[(size_t)M1 * DIM];
__device__ __half g_wq[(size_t)QKVC * DIM];
__device__ __half g_pw[(size_t)DIM * DIM];

// ---------------- PTX helpers (base-target features only) --------------------
__device__ __forceinline__ uint32_t smem_u32(const void* p) {
    uint32_t a;
    asm("{ .reg .u64 t; cvta.to.shared.u64 t, %1; cvt.u32.u64 %0, t; }" : "=r"(a) : "l"(p));
    return a;
}
#define CP_ASYNC16(sa, ga) \
    asm volatile("cp.async.cg.shared.global [%0], [%1], 16;" :: "r"(sa), "l"(ga))
#define CP_COMMIT() asm volatile("cp.async.commit_group;" ::: "memory")
#define CP_WAIT1()  asm volatile("cp.async.wait_group 1;"  ::: "memory")

__device__ __forceinline__ void ldsm_x4(uint32_t& r0, uint32_t& r1, uint32_t& r2,
                                        uint32_t& r3, uint32_t addr) {
    asm volatile("ldmatrix.sync.aligned.m8n8.x4.shared.b16 {%0,%1,%2,%3}, [%4];"
                 : "=r"(r0), "=r"(r1), "=r"(r2), "=r"(r3) : "r"(addr));
}
__device__ __forceinline__ void mma16816(float* d, const uint32_t* a, const uint32_t* b) {
    asm volatile(
        "mma.sync.aligned.m16n8k16.row.col.f32.f16.f16.f32 "
        "{%0,%1,%2,%3}, {%4,%5,%6,%7}, {%8,%9}, {%0,%1,%2,%3};"
        : "+f"(d[0]), "+f"(d[1]), "+f"(d[2]), "+f"(d[3])
        : "r"(a[0]), "r"(a[1]), "r"(a[2]), "r"(a[3]), "r"(b[0]), "r"(b[1]));
}

// ---------------- precision split (fp16 hi/lo) --------------------------------
__device__ __forceinline__ void splith(float x, __half& h, __half& l) {
    h = __float2half_rn(x);
    l = __float2half_rn(x - __half2float(h));
}

__global__ __launch_bounds__(256) void split_kernel(
    const float* __restrict__ in, __half* __restrict__ hi,
    __half* __restrict__ lo, int n4)
{
    int i = blockIdx.x * blockDim.x + threadIdx.x;
    if (i >= n4) return;
    float4 v = ((const float4*)in)[i];
    __half h0, h1, h2, h3, l0, l1, l2, l3;
    splith(v.x, h0, l0); splith(v.y, h1, l1);
    splith(v.z, h2, l2); splith(v.w, h3, l3);
    ((__half2*)hi)[i * 2 + 0] = __halves2half2(h0, h1);
    ((__half2*)hi)[i * 2 + 1] = __halves2half2(h2, h3);
    ((__half2*)lo)[i * 2 + 0] = __halves2half2(l0, l1);
    ((__half2*)lo)[i * 2 + 1] = __halves2half2(l2, l3);
}

__global__ __launch_bounds__(256) void cvt_kernel(
    const float* __restrict__ in, __half* __restrict__ out, int n4)
{
    int i = blockIdx.x * blockDim.x + threadIdx.x;
    if (i >= n4) return;
    float4 v = ((const float4*)in)[i];
    ((__half2*)out)[i * 2 + 0] = __halves2half2(__float2half_rn(v.x), __float2half_rn(v.y));
    ((__half2*)out)[i * 2 + 1] = __halves2half2(__float2half_rn(v.z), __float2half_rn(v.w));
}

// ---------------- fused fp16x2 mma.sync GEMM ---------------------------------
// C[M,N] = (Ah+Al)[M,768] * W[N,768]^T (+bias), fp32 accumulate.
// 128x128 CTA tile, BK=32, 8 warps (warp tile 64x32). Each stage holds
// {Ah, Al, W} tiles; hi and lo MMAs share one B-frag load and one barrier.
// 3-stage cp.async ring, prefetch distance 2. Rows padded to 80B.
#define BKEL   32
#define ROWB   80
#define TILEB  (128 * ROWB)            // 10240 B
#define STAGEB (3 * TILEB)             // Ah+Al+W = 30720 B
#define NSTG   3
#define GSMEM  (NSTG * STAGEB)         // 92160 B
#define NCHUNK (K_TOT / BKEL)          // 24

__global__ __launch_bounds__(256, 2) void gemm_fp16x2_fused(
    const __half* __restrict__ Ah, const __half* __restrict__ Al,
    const __half* __restrict__ W,
    const float* __restrict__ bias, float* __restrict__ C, int ldc)
{
    extern __shared__ __align__(128) char smem[];
    const uint32_t s0 = smem_u32(smem);

    const int tid    = threadIdx.x;
    const int lane   = tid & 31;
    const int wid    = tid >> 5;
    const int warp_m = wid >> 2;       // 0..1
    const int warp_n = wid & 3;        // 0..3
    const int bm     = blockIdx.y * 128;
    const int bn     = blockIdx.x * 128;

    const int lrow0 = tid >> 2;          // 0..63
    const int lseg  = (tid & 3) * 16;

    auto load_chunk = [&](int c, int stage) {
        const int k0 = c * BKEL;
        const __half* gAh = Ah + (size_t)bm * K_TOT + k0;
        const __half* gAl = Al + (size_t)bm * K_TOT + k0;
        const __half* gW  = W  + (size_t)bn * K_TOT + k0;
        const uint32_t d0 = s0 + stage * STAGEB;
        #pragma unroll
        for (int i = 0; i < 2; i++) {
            const int row = lrow0 + i * 64;
            const uint32_t so = row * ROWB + lseg;
            const size_t   go = (size_t)row * K_TOT;
            CP_ASYNC16(d0 + so,             (const char*)(gAh + go) + lseg);
            CP_ASYNC16(d0 + TILEB + so,     (const char*)(gAl + go) + lseg);
            CP_ASYNC16(d0 + 2 * TILEB + so, (const char*)(gW  + go) + lseg);
        }
    };

    float acc[4][4][4];
    #pragma unroll
    for (int mi = 0; mi < 4; mi++)
        #pragma unroll
        for (int nj = 0; nj < 4; nj++)
            #pragma unroll
            for (int e = 0; e < 4; e++) acc[mi][nj][e] = 0.f;

    load_chunk(0, 0); CP_COMMIT();
    load_chunk(1, 1); CP_COMMIT();

    const uint32_t a_row  = warp_m * 64 + (lane & 15);
    const uint32_t a_coff = (lane >> 4) * 16;
    const uint32_t b_row  = warp_n * 32 + ((lane >> 4) << 3) + (lane & 7);
    const uint32_t b_coff = ((lane >> 3) & 1) * 16;

    #pragma unroll 1
    for (int c = 0; c < NCHUNK; c++) {
        CP_WAIT1();                     // chunk c's group complete
        __syncthreads();                // all warps done with stage (c-1)%3
        const int stage = c % NSTG;
        const uint32_t sAh = s0 + stage * STAGEB;
        const uint32_t sAl = sAh + TILEB;
        const uint32_t sW  = sAh + 2 * TILEB;

        #pragma unroll
        for (int kk = 0; kk < 2; kk++) {
            uint32_t b[4][2];
            #pragma unroll
            for (int nj2 = 0; nj2 < 2; nj2++) {
                uint32_t r0, r1, r2, r3;
                ldsm_x4(r0, r1, r2, r3,
                        sW + (b_row + nj2 * 16) * ROWB + kk * 32 + b_coff);
                b[nj2 * 2 + 0][0] = r0; b[nj2 * 2 + 0][1] = r1;
                b[nj2 * 2 + 1][0] = r2; b[nj2 * 2 + 1][1] = r3;
            }
            uint32_t a[4][4];
            #pragma unroll
            for (int mi = 0; mi < 4; mi++)
                ldsm_x4(a[mi][0], a[mi][1], a[mi][2], a[mi][3],
                        sAh + (a_row + mi * 16) * ROWB + kk * 32 + a_coff);
            #pragma unroll
            for (int mi = 0; mi < 4; mi++)
                #pragma unroll
                for (int nj = 0; nj < 4; nj++)
                    mma16816(acc[mi][nj], a[mi], b[nj]);
            #pragma unroll
            for (int mi = 0; mi < 4; mi++)
                ldsm_x4(a[mi][0], a[mi][1], a[mi][2], a[mi][3],
                        sAl + (a_row + mi * 16) * ROWB + kk * 32 + a_coff);
            #pragma unroll
            for (int mi = 0; mi < 4; mi++)
                #pragma unroll
                for (int nj = 0; nj < 4; nj++)
                    mma16816(acc[mi][nj], a[mi], b[nj]);
        }
        if (c + 2 < NCHUNK) load_chunk(c + 2, (c + 2) % NSTG);
        CP_COMMIT();
    }

    const int er = lane >> 2;
    const int ec = (lane & 3) * 2;
    #pragma unroll
    for (int mi = 0; mi < 4; mi++) {
        const int r0 = bm + warp_m * 64 + mi * 16 + er;
        #pragma unroll
        for (int nj = 0; nj < 4; nj++) {
            const int col = bn + warp_n * 32 + nj * 8 + ec;
            float2 v0 = make_float2(acc[mi][nj][0], acc[mi][nj][1]);
            float2 v1 = make_float2(acc[mi][nj][2], acc[mi][nj][3]);
            if (bias) {
                const float2 bv = *(const float2*)(bias + col);
                v0.x += bv.x; v0.y += bv.y;
                v1.x += bv.x; v1.y += bv.y;
            }
            *(float2*)(C + (size_t)r0 * ldc + col)       = v0;
            *(float2*)(C + (size_t)(r0 + 8) * ldc + col) = v1;
        }
    }
}

// ---------------- local attention (3x3 neighborhood, exact softmax) ----------
__global__ __launch_bounds__(NH * 32) void local_attn_kernel(
    const float* __restrict__ Y, const float* __restrict__ rpb,
    __half* __restrict__ Ohi, __half* __restrict__ Olo)
{
    const int bq   = blockIdx.x;
    const int q    = bq % NTOK;
    const int qi   = q / WS, qj = q % WS;
    const int h    = threadIdx.x >> 5;
    const int lane = threadIdx.x & 31;

    const size_t base = (size_t)bq * QKVC + h * HD;
    float2 qv = ((const float2*)(Y + base))[lane];
    qv.x *= 0.125f; qv.y *= 0.125f;

    float  logit[9];
    float2 vv[9];
    #pragma unroll
    for (int t = 0; t < 9; t++) {
        const int di = t / 3 - 1, dj = t % 3 - 1;
        const int ki = qi + di, kj = qj + dj;
        const bool ok = ((unsigned)ki < WS) && ((unsigned)kj < WS);
        float  lg = -1e30f;
        float2 v2 = make_float2(0.f, 0.f);
        if (ok) {
            const size_t kbase = (size_t)(bq + di * WS + dj) * QKVC + h * HD;
            float2 kv = ((const float2*)(Y + kbase + DIM))[lane];
            v2        = ((const float2*)(Y + kbase + 2 * DIM))[lane];
            float p = qv.x * kv.x + qv.y * kv.y;
            #pragma unroll
            for (int off = 16; off > 0; off >>= 1)
                p += __shfl_xor_sync(0xffffffffu, p, off);
            const int rel = (13 - di) * 27 + (13 - dj);
            lg = p + rpb[rel * NH + h];
        }
        logit[t] = lg;
        vv[t]    = v2;
    }

    float m = logit[0];
    #pragma unroll
    for (int t = 1; t < 9; t++) m = fmaxf(m, logit[t]);
    float den = 0.f;
    float2 acc = make_float2(0.f, 0.f);
    #pragma unroll
    for (int t = 0; t < 9; t++) {
        float e = __expf(logit[t] - m);
        den  += e;
        acc.x = fmaf(e, vv[t].x, acc.x);
        acc.y = fmaf(e, vv[t].y, acc.y);
    }
    const float inv = 1.f / den;
    acc.x *= inv; acc.y *= inv;

    __half hx, lx, hy, ly;
    splith(acc.x, hx, lx);
    splith(acc.y, hy, ly);
    const size_t obase = (size_t)bq * DIM + h * HD;
    ((__half2*)(Ohi + obase))[lane] = __halves2half2(hx, hy);
    ((__half2*)(Olo + obase))[lane] = __halves2half2(lx, ly);
}

// ---------------------------------------------------------------------------
extern "C" void kernel_launch(void* const* d_in, const int* in_sizes, int n_in,
                              void* d_out, int out_size)
{
    const float* x      = (const float*)d_in[0];
    const float* w_qkv  = (const float*)d_in[1];
    const float* rpb    = (const float*)d_in[2];
    const float* proj_w = (const float*)d_in[3];
    const float* proj_b = (const float*)d_in[4];
    float* out = (float*)d_out;

    float *qkv;
    __half *xh, *xl, *ah, *al, *wq, *pw;
    cudaGetSymbolAddress((void**)&qkv, g_qkv);
    cudaGetSymbolAddress((void**)&xh,  g_xh);
    cudaGetSymbolAddress((void**)&xl,  g_xl);
    cudaGetSymbolAddress((void**)&ah,  g_ah);
    cudaGetSymbolAddress((void**)&al,  g_al);
    cudaGetSymbolAddress((void**)&wq,  g_wq);
    cudaGetSymbolAddress((void**)&pw,  g_pw);

    cudaFuncSetAttribute(gemm_fp16x2_fused,
                         cudaFuncAttributeMaxDynamicSharedMemorySize, GSMEM);

    {
        int n4 = M1 * DIM / 4;
        split_kernel<<<(n4 + 255) / 256, 256>>>(x, xh, xl, n4);
    }
    {
        int n4 = QKVC * DIM / 4;
        cvt_kernel<<<(n4 + 255) / 256, 256>>>(w_qkv, wq, n4);
    }
    {
        int n4 = DIM * DIM / 4;
        cvt_kernel<<<(n4 + 255) / 256, 256>>>(proj_w, pw, n4);
    }

    dim3 g1(QKVC / 128, M1 / 128);   // 18 x 392
    gemm_fp16x2_fused<<<g1, 256, GSMEM>>>(xh, xl, wq, nullptr, qkv, QKVC);

    local_attn_kernel<<<M1, NH * 32>>>(qkv, rpb, ah, al);

    dim3 g3(DIM / 128, M1 / 128);    // 6 x 392
    gemm_fp16x2_fused<<<g3, 256, GSMEM>>>(ah, al, pw, proj_b, out, DIM);
}

// round 6
// speedup vs baseline: 5.2092x; 1.4952x over previous
#include <cuda_runtime.h>
#include <cuda_fp16.h>
#include <cstdint>

#define WS    14
#define NTOK  196
#define DIM   768
#define NH    12
#define HD    64
#define BATCH 256
#define M1    (BATCH * NTOK)   // 50176
#define QKVC  (3 * DIM)        // 2304
#define K_TOT 768

// ---------------- scratch (static device arrays; no runtime alloc) ----------
__device__ float  g_qkv[(size_t)M1 * QKVC];
__device__ __half g_x16[(size_t)M1 * DIM];
__device__ __half g_a16[(size_t)M1 * DIM];
__device__ __half g_wq[(size_t)QKVC * DIM];
__device__ __half g_pw[(size_t)DIM * DIM];

// ---------------- PTX helpers (base-target features only) --------------------
__device__ __forceinline__ uint32_t smem_u32(const void* p) {
    uint32_t a;
    asm("{ .reg .u64 t; cvta.to.shared.u64 t, %1; cvt.u32.u64 %0, t; }" : "=r"(a) : "l"(p));
    return a;
}
#define CP_ASYNC16(sa, ga) \
    asm volatile("cp.async.cg.shared.global [%0], [%1], 16;" :: "r"(sa), "l"(ga))
#define CP_COMMIT() asm volatile("cp.async.commit_group;" ::: "memory")
#define CP_WAIT1()  asm volatile("cp.async.wait_group 1;"  ::: "memory")

__device__ __forceinline__ void ldsm_x4(uint32_t& r0, uint32_t& r1, uint32_t& r2,
                                        uint32_t& r3, uint32_t addr) {
    asm volatile("ldmatrix.sync.aligned.m8n8.x4.shared.b16 {%0,%1,%2,%3}, [%4];"
                 : "=r"(r0), "=r"(r1), "=r"(r2), "=r"(r3) : "r"(addr));
}
__device__ __forceinline__ void mma16816(float* d, const uint32_t* a, const uint32_t* b) {
    asm volatile(
        "mma.sync.aligned.m16n8k16.row.col.f32.f16.f16.f32 "
        "{%0,%1,%2,%3}, {%4,%5,%6,%7}, {%8,%9}, {%0,%1,%2,%3};"
        : "+f"(d[0]), "+f"(d[1]), "+f"(d[2]), "+f"(d[3])
        : "r"(a[0]), "r"(a[1]), "r"(a[2]), "r"(a[3]), "r"(b[0]), "r"(b[1]));
}

// ---------------- fp32 -> fp16 convert ----------------------------------------
__global__ __launch_bounds__(256) void cvt_kernel(
    const float* __restrict__ in, __half* __restrict__ out, int n4)
{
    int i = blockIdx.x * blockDim.x + threadIdx.x;
    if (i >= n4) return;
    float4 v = ((const float4*)in)[i];
    ((__half2*)out)[i * 2 + 0] = __halves2half2(__float2half_rn(v.x), __float2half_rn(v.y));
    ((__half2*)out)[i * 2 + 1] = __halves2half2(__float2half_rn(v.z), __float2half_rn(v.w));
}

// ---------------- fp16 mma.sync GEMM ------------------------------------------
// C[M,N] = A[M,768] * W[N,768]^T (+bias), fp32 accumulate.
// 128x128 CTA tile, BK=64, 8 warps (warp tile 64x32), 3-stage cp.async ring,
// one __syncthreads per 64-wide chunk. Rows padded to 144B (conflict-free ldsm).
#define BKEL   64
#define ROWB   144
#define TILEB  (128 * ROWB)            // 18432 B
#define STAGEB (2 * TILEB)             // A+W = 36864 B
#define NSTG   3
#define GSMEM  (NSTG * STAGEB)         // 110592 B
#define NCHUNK (K_TOT / BKEL)          // 12

__global__ __launch_bounds__(256, 2) void gemm_fp16_mma(
    const __half* __restrict__ A, const __half* __restrict__ W,
    const float* __restrict__ bias, float* __restrict__ C, int ldc)
{
    extern __shared__ __align__(128) char smem[];
    const uint32_t s0 = smem_u32(smem);

    const int tid    = threadIdx.x;
    const int lane   = tid & 31;
    const int wid    = tid >> 5;
    const int warp_m = wid >> 2;       // 0..1
    const int warp_n = wid & 3;        // 0..3
    const int bm     = blockIdx.y * 128;
    const int bn     = blockIdx.x * 128;

    const int lrow0 = tid >> 3;          // 0..31
    const int lseg  = (tid & 7) * 16;    // 16B segment within 128B row

    auto load_chunk = [&](int c, int stage) {
        const int k0 = c * BKEL;
        const __half* gA = A + (size_t)bm * K_TOT + k0;
        const __half* gW = W + (size_t)bn * K_TOT + k0;
        const uint32_t dA = s0 + stage * STAGEB;
        const uint32_t dW = dA + TILEB;
        #pragma unroll
        for (int p = 0; p < 4; p++) {
            const int row = lrow0 + p * 32;
            const uint32_t so = row * ROWB + lseg;
            const size_t   go = (size_t)row * K_TOT;
            CP_ASYNC16(dA + so, (const char*)(gA + go) + lseg);
            CP_ASYNC16(dW + so, (const char*)(gW + go) + lseg);
        }
    };

    float acc[4][4][4];
    #pragma unroll
    for (int mi = 0; mi < 4; mi++)
        #pragma unroll
        for (int nj = 0; nj < 4; nj++)
            #pragma unroll
            for (int e = 0; e < 4; e++) acc[mi][nj][e] = 0.f;

    load_chunk(0, 0); CP_COMMIT();
    load_chunk(1, 1); CP_COMMIT();

    const uint32_t a_row  = warp_m * 64 + (lane & 15);
    const uint32_t a_coff = (lane >> 4) * 16;
    const uint32_t b_row  = warp_n * 32 + ((lane >> 4) << 3) + (lane & 7);
    const uint32_t b_coff = ((lane >> 3) & 1) * 16;

    #pragma unroll 1
    for (int c = 0; c < NCHUNK; c++) {
        CP_WAIT1();                     // chunk c's data resident
        __syncthreads();                // all warps done reading stage (c-1)%3
        // issue next loads first so cp.async overlaps the compute below
        if (c + 2 < NCHUNK) load_chunk(c + 2, (c + 2) % NSTG);
        CP_COMMIT();

        const int stage = c % NSTG;
        const uint32_t sA = s0 + stage * STAGEB;
        const uint32_t sW = sA + TILEB;

        #pragma unroll
        for (int kk = 0; kk < 4; kk++) {
            uint32_t b[4][2];
            #pragma unroll
            for (int nj2 = 0; nj2 < 2; nj2++) {
                uint32_t r0, r1, r2, r3;
                ldsm_x4(r0, r1, r2, r3,
                        sW + (b_row + nj2 * 16) * ROWB + kk * 32 + b_coff);
                b[nj2 * 2 + 0][0] = r0; b[nj2 * 2 + 0][1] = r1;
                b[nj2 * 2 + 1][0] = r2; b[nj2 * 2 + 1][1] = r3;
            }
            uint32_t a[4][4];
            #pragma unroll
            for (int mi = 0; mi < 4; mi++)
                ldsm_x4(a[mi][0], a[mi][1], a[mi][2], a[mi][3],
                        sA + (a_row + mi * 16) * ROWB + kk * 32 + a_coff);
            #pragma unroll
            for (int mi = 0; mi < 4; mi++)
                #pragma unroll
                for (int nj = 0; nj < 4; nj++)
                    mma16816(acc[mi][nj], a[mi], b[nj]);
        }
    }

    const int er = lane >> 2;
    const int ec = (lane & 3) * 2;
    #pragma unroll
    for (int mi = 0; mi < 4; mi++) {
        const int r0 = bm + warp_m * 64 + mi * 16 + er;
        #pragma unroll
        for (int nj = 0; nj < 4; nj++) {
            const int col = bn + warp_n * 32 + nj * 8 + ec;
            float2 v0 = make_float2(acc[mi][nj][0], acc[mi][nj][1]);
            float2 v1 = make_float2(acc[mi][nj][2], acc[mi][nj][3]);
            if (bias) {
                const float2 bv = *(const float2*)(bias + col);
                v0.x += bv.x; v0.y += bv.y;
                v1.x += bv.x; v1.y += bv.y;
            }
            *(float2*)(C + (size_t)r0 * ldc + col)       = v0;
            *(float2*)(C + (size_t)(r0 + 8) * ldc + col) = v1;
        }
    }
}

// ---------------- local attention (3x3 neighborhood, exact softmax) ----------
__global__ __launch_bounds__(NH * 32) void local_attn_kernel(
    const float* __restrict__ Y, const float* __restrict__ rpb,
    __half* __restrict__ O)
{
    const int bq   = blockIdx.x;
    const int q    = bq % NTOK;
    const int qi   = q / WS, qj = q % WS;
    const int h    = threadIdx.x >> 5;
    const int lane = threadIdx.x & 31;

    const size_t base = (size_t)bq * QKVC + h * HD;
    float2 qv = ((const float2*)(Y + base))[lane];
    qv.x *= 0.125f; qv.y *= 0.125f;

    float  logit[9];
    float2 vv[9];
    #pragma unroll
    for (int t = 0; t < 9; t++) {
        const int di = t / 3 - 1, dj = t % 3 - 1;
        const int ki = qi + di, kj = qj + dj;
        const bool ok = ((unsigned)ki < WS) && ((unsigned)kj < WS);
        float  lg = -1e30f;
        float2 v2 = make_float2(0.f, 0.f);
        if (ok) {
            const size_t kbase = (size_t)(bq + di * WS + dj) * QKVC + h * HD;
            float2 kv = ((const float2*)(Y + kbase + DIM))[lane];
            v2        = ((const float2*)(Y + kbase + 2 * DIM))[lane];
            float p = qv.x * kv.x + qv.y * kv.y;
            #pragma unroll
            for (int off = 16; off > 0; off >>= 1)
                p += __shfl_xor_sync(0xffffffffu, p, off);
            const int rel = (13 - di) * 27 + (13 - dj);
            lg = p + rpb[rel * NH + h];
        }
        logit[t] = lg;
        vv[t]    = v2;
    }

    float m = logit[0];
    #pragma unroll
    for (int t = 1; t < 9; t++) m = fmaxf(m, logit[t]);
    float den = 0.f;
    float2 acc = make_float2(0.f, 0.f);
    #pragma unroll
    for (int t = 0; t < 9; t++) {
        float e = __expf(logit[t] - m);
        den  += e;
        acc.x = fmaf(e, vv[t].x, acc.x);
        acc.y = fmaf(e, vv[t].y, acc.y);
    }
    const float inv = 1.f / den;
    acc.x *= inv; acc.y *= inv;

    const size_t obase = (size_t)bq * DIM + h * HD;
    ((__half2*)(O + obase))[lane] =
        __halves2half2(__float2half_rn(acc.x), __float2half_rn(acc.y));
}

// ---------------------------------------------------------------------------
extern "C" void kernel_launch(void* const* d_in, const int* in_sizes, int n_in,
                              void* d_out, int out_size)
{
    const float* x      = (const float*)d_in[0];
    const float* w_qkv  = (const float*)d_in[1];
    const float* rpb    = (const float*)d_in[2];
    const float* proj_w = (const float*)d_in[3];
    const float* proj_b = (const float*)d_in[4];
    float* out = (float*)d_out;

    float *qkv;
    __half *x16, *a16, *wq, *pw;
    cudaGetSymbolAddress((void**)&qkv, g_qkv);
    cudaGetSymbolAddress((void**)&x16, g_x16);
    cudaGetSymbolAddress((void**)&a16, g_a16);
    cudaGetSymbolAddress((void**)&wq,  g_wq);
    cudaGetSymbolAddress((void**)&pw,  g_pw);

    cudaFuncSetAttribute(gemm_fp16_mma,
                         cudaFuncAttributeMaxDynamicSharedMemorySize, GSMEM);

    {
        int n4 = M1 * DIM / 4;
        cvt_kernel<<<(n4 + 255) / 256, 256>>>(x, x16, n4);
    }
    {
        int n4 = QKVC * DIM / 4;
        cvt_kernel<<<(n4 + 255) / 256, 256>>>(w_qkv, wq, n4);
    }
    {
        int n4 = DIM * DIM / 4;
        cvt_kernel<<<(n4 + 255) / 256, 256>>>(proj_w, pw, n4);
    }

    dim3 g1(QKVC / 128, M1 / 128);   // 18 x 392
    gemm_fp16_mma<<<g1, 256, GSMEM>>>(x16, wq, nullptr, qkv, QKVC);

    local_attn_kernel<<<M1, NH * 32>>>(qkv, rpb, a16);

    dim3 g3(DIM / 128, M1 / 128);    // 6 x 392
    gemm_fp16_mma<<<g3, 256, GSMEM>>>(a16, pw, proj_b, out, DIM);
}